// round 2
// baseline (speedup 1.0000x reference)
#include <cuda_runtime.h>

// Problem dims
#define BATCH 512
#define LSEQ  256     // H*W = 16*16
#define CIN   32
#define HID   128
#define OUTD  512

// ---------------- scratch (static device globals; no runtime allocation) ---
__device__ float d_Wc[HID * CIN];                       // folded W_ih @ W_in  (128x32)
__device__ float d_bc[HID];                             // folded bias
__device__ float d_pre[(size_t)BATCH * LSEQ * HID];     // 64 MB, layout [b][t][j]
__device__ float d_hs [(size_t)BATCH * LSEQ * HID];     // 64 MB, layout [b][t][j]
__device__ float d_pooled[BATCH * HID];

// ---------------- f32x2 helpers (Blackwell packed fp32 FMA) ----------------
__device__ __forceinline__ unsigned long long pack2(float a, float b) {
    unsigned long long r;
    asm("mov.b64 %0, {%1, %2};" : "=l"(r) : "f"(a), "f"(b));
    return r;
}
__device__ __forceinline__ void unpack2(unsigned long long v, float& a, float& b) {
    asm("mov.b64 {%0, %1}, %2;" : "=f"(a), "=f"(b) : "l"(v));
}
__device__ __forceinline__ void ffma2(unsigned long long& acc,
                                      unsigned long long a, unsigned long long b) {
    asm("fma.rn.f32x2 %0, %1, %2, %0;" : "+l"(acc) : "l"(a), "l"(b));
}
__device__ __forceinline__ unsigned long long fadd2(unsigned long long a,
                                                    unsigned long long b) {
    unsigned long long r;
    asm("add.rn.f32x2 %0, %1, %2;" : "=l"(r) : "l"(a), "l"(b));
    return r;
}

// ---------------------------------------------------------------------------
// Kernel A: fold the two input linears.
//   Wc[j][c] = sum_m W_ih[j][m] * W_in[m][c]   (128x64 @ 64x32)
//   bc[j]    = b_ih[j] + sum_m W_ih[j][m] * b_in[m]
// ---------------------------------------------------------------------------
__global__ void combine_kernel(const float* __restrict__ W_in,
                               const float* __restrict__ b_in,
                               const float* __restrict__ W_ih,
                               const float* __restrict__ b_ih) {
    int idx = blockIdx.x * blockDim.x + threadIdx.x;
    if (idx < HID * CIN) {
        int j = idx >> 5, c = idx & 31;
        float s = 0.f;
        #pragma unroll 8
        for (int m = 0; m < 64; m++) s += W_ih[j * 64 + m] * W_in[m * 32 + c];
        d_Wc[idx] = s;
    }
    if (idx < HID) {
        float s = b_ih[idx];
        #pragma unroll 8
        for (int m = 0; m < 64; m++) s += W_ih[idx * 64 + m] * b_in[m];
        d_bc[idx] = s;
    }
}

// ---------------------------------------------------------------------------
// Kernel B: pre[b][t][j] = bc[j] + sum_c Wc[j][c] * x[b][c][t]
// grid (8, 512): 32 t's per CTA per batch. 256 threads: j = tid&127, th = tid>>7.
// Each thread produces 16 t values as 8 f32x2 pairs. x tile staged in smem.
// ---------------------------------------------------------------------------
__global__ void __launch_bounds__(256) pre_kernel(const float* __restrict__ x) {
    __shared__ __align__(16) float xs[32 * 32];   // [c][tt]
    int tid = threadIdx.x;
    int b = blockIdx.y;
    int t0 = blockIdx.x * 32;

    #pragma unroll
    for (int i = 0; i < 4; i++) {
        int idx = i * 256 + tid;
        int c = idx >> 5, tt = idx & 31;
        xs[idx] = x[(b * 32 + c) * 256 + t0 + tt];
    }

    int j = tid & 127;
    int th = tid >> 7;

    unsigned long long wd[32];   // duplicated weight pairs (w,w)
    #pragma unroll
    for (int c4 = 0; c4 < 8; c4++) {
        float4 w = *(const float4*)&d_Wc[j * 32 + c4 * 4];
        wd[c4 * 4 + 0] = pack2(w.x, w.x);
        wd[c4 * 4 + 1] = pack2(w.y, w.y);
        wd[c4 * 4 + 2] = pack2(w.z, w.z);
        wd[c4 * 4 + 3] = pack2(w.w, w.w);
    }
    float bcj = d_bc[j];
    unsigned long long bias2 = pack2(bcj, bcj);

    __syncthreads();

    int tbase = th * 16;
    #pragma unroll
    for (int p = 0; p < 8; p++) {
        unsigned long long acc = bias2;
        const float* xb = xs + tbase + 2 * p;
        #pragma unroll
        for (int c = 0; c < 32; c++) {
            unsigned long long xv = *(const unsigned long long*)(xb + c * 32);
            ffma2(acc, wd[c], xv);
        }
        float lo, hi;
        unpack2(acc, lo, hi);
        int t = t0 + tbase + 2 * p;
        d_pre[(b * 256 + t) * 128 + j]     = lo;
        d_pre[(b * 256 + t + 1) * 128 + j] = hi;
    }
}

// ---------------------------------------------------------------------------
// Kernel C: the sequential RNN scan.
//   h_{t} = tanh(pre[b][t][:] + W_hh @ h_{t-1} + b_hh), written to d_hs.
// 128 CTAs x 4 batch rows. 512 threads: tid = 4*j + kc.
// Thread (j,kc) keeps W_hh[j][kc*32 .. kc*32+31] in registers as 16 f32x2 pairs.
// h lives in padded smem (row stride 144 floats, chunk base kc*36) so the four
// kc-slices hit distinct bank groups (conflict-free LDS.128 + 8-way broadcast).
// 4-lane shuffle reduction combines the kc partials; lane kc finalizes row kc.
// ---------------------------------------------------------------------------
__global__ void __launch_bounds__(512, 1) rnn_kernel(const float* __restrict__ h0,
                                                     const float* __restrict__ W_hh,
                                                     const float* __restrict__ b_hh) {
    __shared__ __align__(16) float hsm[4 * 144];

    int tid = threadIdx.x;
    int j  = tid >> 2;
    int kc = tid & 3;
    int r0 = blockIdx.x * 4;

    // W slice into registers (pairs, element order matches smem h pairs)
    unsigned long long wp[16];
    {
        const float* wrow = W_hh + j * 128 + kc * 32;
        #pragma unroll
        for (int i4 = 0; i4 < 8; i4++) {
            float4 w = *(const float4*)(wrow + i4 * 4);
            wp[i4 * 2 + 0] = pack2(w.x, w.y);
            wp[i4 * 2 + 1] = pack2(w.z, w.w);
        }
    }
    float bj = b_hh[j];

    // init h state
    {
        int r = tid >> 7, k = tid & 127;
        float v = h0[(r0 + r) * 128 + k];
        hsm[r * 144 + (k >> 5) * 36 + (k & 31)] = v;
    }
    __syncthreads();

    int pbase = r0 * (256 * 128);
    int pof   = kc * (256 * 128) + j;   // this thread finalizes row kc, output j

    for (int t = 0; t < 256; t++) {
        // prefetch this step's pre value (used ~500 cycles later)
        float pv = d_pre[pbase + pof + t * 128];

        float s[4];
        #pragma unroll
        for (int r = 0; r < 4; r++) {
            const ulonglong2* hb =
                reinterpret_cast<const ulonglong2*>(hsm + r * 144 + kc * 36);
            unsigned long long acc0 = 0ull, acc1 = 0ull;  // (0.f,0.f)
            #pragma unroll
            for (int ic = 0; ic < 8; ic++) {
                ulonglong2 hv = hb[ic];
                ffma2(acc0, wp[2 * ic],     hv.x);
                ffma2(acc1, wp[2 * ic + 1], hv.y);
            }
            unsigned long long accs = fadd2(acc0, acc1);
            float lo, hi;
            unpack2(accs, lo, hi);
            float v = lo + hi;
            v += __shfl_xor_sync(0xffffffffu, v, 1);
            v += __shfl_xor_sync(0xffffffffu, v, 2);
            s[r] = v;
        }

        float sel = (kc == 0) ? s[0] : (kc == 1) ? s[1] : (kc == 2) ? s[2] : s[3];
        float z = sel + pv + bj;
        // tanh(z) = 1 - 2/(exp(2z)+1); saturates correctly at +/-1 for |z| large
        float e = __expf(2.0f * z);
        float hval = 1.0f - __fdividef(2.0f, e + 1.0f);

        __syncthreads();  // all reads of h_{t-1} done
        hsm[kc * 144 + (j >> 5) * 36 + (j & 31)] = hval;
        d_hs[pbase + pof + t * 128] = hval;
        __syncthreads();  // h_t visible for next step
    }
}

// ---------------------------------------------------------------------------
// Kernel D: bilinear upsample (16->32, align_corners) + hardswish + mean pool.
// grid (4, 512): CTA = (32-wide j tile, batch b). 256 threads = 32 jj x 8 p.
// Stage the 256x32 h tile in smem; thread (jj,p) handles output rows oy=8*ii+p.
// ---------------------------------------------------------------------------
__global__ void __launch_bounds__(256) pool_kernel() {
    __shared__ __align__(16) float ht[256 * 32];  // [t][jj]
    __shared__ int   xo0[32], xo1[32];
    __shared__ float wxs[32];
    __shared__ float partial[8][32];

    int tid = threadIdx.x;
    int b  = blockIdx.y;
    int j0 = blockIdx.x * 32;

    #pragma unroll 4
    for (int i = 0; i < 32; i++) {
        int idx = i * 256 + tid;
        int t = idx >> 5, jj = idx & 31;
        ht[idx] = d_hs[(b * 256 + t) * 128 + j0 + jj];
    }
    if (tid < 32) {
        float xsf = (float)(tid * 15) / 31.0f;   // matches jax arange*15/31 exactly
        int x0 = (int)xsf;
        float wx = xsf - (float)x0;
        int x1 = min(x0 + 1, 15);
        xo0[tid] = x0 * 32;
        xo1[tid] = x1 * 32;
        wxs[tid] = wx;
    }
    __syncthreads();

    int jj = tid & 31, p = tid >> 5;
    float acc = 0.f;

    #pragma unroll
    for (int ii = 0; ii < 4; ii++) {
        int oy = ii * 8 + p;
        float ysf = (float)(oy * 15) / 31.0f;
        int y0 = (int)ysf;
        float wy = ysf - (float)y0;
        int y1 = min(y0 + 1, 15);
        const float* rA = ht + y0 * 512 + jj;  // (y0*16)*32
        const float* rB = ht + y1 * 512 + jj;
        #pragma unroll 8
        for (int ox = 0; ox < 32; ox++) {
            int o0 = xo0[ox], o1 = xo1[ox];
            float wx = wxs[ox];
            float a00 = rA[o0], a10 = rB[o0];
            float a01 = rA[o1], a11 = rB[o1];
            float top = fmaf(a10 - a00, wy, a00);
            float bot = fmaf(a11 - a01, wy, a01);
            float v   = fmaf(bot - top, wx, top);
            acc += v * fminf(fmaxf(v + 3.0f, 0.0f), 6.0f);
        }
    }
    partial[p][jj] = acc;
    __syncthreads();
    if (p == 0) {
        float s = 0.f;
        #pragma unroll
        for (int q = 0; q < 8; q++) s += partial[q][jj];
        d_pooled[b * 128 + j0 + jj] = s * (1.0f / (6.0f * 1024.0f));
    }
}

// ---------------------------------------------------------------------------
// Kernel E: out[b][o] = b_out[o] + sum_j pooled[b][j] * W_out[o][j]
// grid (8, 8): 64x64 output tiles, 256 threads, 4x4 microtiles, k in 2 chunks.
// ---------------------------------------------------------------------------
__global__ void __launch_bounds__(256) out_gemm(const float* __restrict__ W_out,
                                                const float* __restrict__ b_out,
                                                float* __restrict__ out) {
    __shared__ float ws[64][65];
    __shared__ float ps[64][65];

    int tid = threadIdx.x;
    int o0 = blockIdx.x * 64, b0 = blockIdx.y * 64;
    int to = (tid & 15) * 4;
    int tb = (tid >> 4) * 4;

    float acc[4][4] = {};

    for (int k0 = 0; k0 < 128; k0 += 64) {
        __syncthreads();
        #pragma unroll
        for (int i = 0; i < 16; i++) {
            int idx = i * 256 + tid;
            int r = idx >> 6, c = idx & 63;
            ws[r][c] = W_out[(o0 + r) * 128 + k0 + c];
            ps[r][c] = d_pooled[(b0 + r) * 128 + k0 + c];
        }
        __syncthreads();

        #pragma unroll 4
        for (int k = 0; k < 64; k++) {
            float wv[4], pvv[4];
            #pragma unroll
            for (int m = 0; m < 4; m++) { wv[m] = ws[to + m][k]; pvv[m] = ps[tb + m][k]; }
            #pragma unroll
            for (int mb = 0; mb < 4; mb++)
                #pragma unroll
                for (int mo = 0; mo < 4; mo++)
                    acc[mb][mo] = fmaf(pvv[mb], wv[mo], acc[mb][mo]);
        }
    }

    #pragma unroll
    for (int mb = 0; mb < 4; mb++)
        #pragma unroll
        for (int mo = 0; mo < 4; mo++)
            out[(b0 + tb + mb) * 512 + o0 + to + mo] = acc[mb][mo] + b_out[o0 + to + mo];
}

// ---------------------------------------------------------------------------
extern "C" void kernel_launch(void* const* d_in, const int* in_sizes, int n_in,
                              void* d_out, int out_size) {
    const float* x     = (const float*)d_in[0];
    const float* h0    = (const float*)d_in[1];
    const float* W_in  = (const float*)d_in[2];
    const float* b_in  = (const float*)d_in[3];
    const float* W_ih  = (const float*)d_in[4];
    const float* b_ih  = (const float*)d_in[5];
    const float* W_hh  = (const float*)d_in[6];
    const float* b_hh  = (const float*)d_in[7];
    const float* W_out = (const float*)d_in[8];
    const float* b_out = (const float*)d_in[9];
    float* out = (float*)d_out;

    combine_kernel<<<16, 256>>>(W_in, b_in, W_ih, b_ih);
    pre_kernel<<<dim3(8, 512), 256>>>(x);
    rnn_kernel<<<128, 512>>>(h0, W_hh, b_hh);
    pool_kernel<<<dim3(4, 512), 256>>>();
    out_gemm<<<dim3(8, 8), 256>>>(W_out, b_out, out);
}

// round 3
// speedup vs baseline: 1.7059x; 1.7059x over previous
#include <cuda_runtime.h>

// Problem dims
#define BATCH 512
#define LSEQ  256     // H*W = 16*16
#define CIN   32
#define HID   128
#define OUTD  512

// ---------------- scratch (static device globals; no runtime allocation) ---
__device__ float d_Wc[HID * CIN];                       // folded W_ih @ W_in  (128x32)
__device__ float d_bc[HID];                             // folded bias (b_ih@.. + b_hh)
__device__ float d_pre[(size_t)BATCH * LSEQ * HID];     // 64 MB, layout [b][t][j]
__device__ float d_hs [(size_t)BATCH * LSEQ * HID];     // 64 MB, layout [b][t][j]
__device__ float d_pooled[BATCH * HID];

// ---------------- f32x2 helpers (Blackwell packed fp32 FMA) ----------------
__device__ __forceinline__ unsigned long long pack2(float a, float b) {
    unsigned long long r;
    asm("mov.b64 %0, {%1, %2};" : "=l"(r) : "f"(a), "f"(b));
    return r;
}
__device__ __forceinline__ void unpack2(unsigned long long v, float& a, float& b) {
    asm("mov.b64 {%0, %1}, %2;" : "=f"(a), "=f"(b) : "l"(v));
}
__device__ __forceinline__ void ffma2(unsigned long long& acc,
                                      unsigned long long a, unsigned long long b) {
    asm("fma.rn.f32x2 %0, %1, %2, %0;" : "+l"(acc) : "l"(a), "l"(b));
}
__device__ __forceinline__ unsigned long long fadd2(unsigned long long a,
                                                    unsigned long long b) {
    unsigned long long r;
    asm("add.rn.f32x2 %0, %1, %2;" : "=l"(r) : "l"(a), "l"(b));
    return r;
}

// ---------------------------------------------------------------------------
// Kernel A: fold the two input linears + b_hh.
//   Wc[j][c] = sum_m W_ih[j][m] * W_in[m][c]
//   bc[j]    = b_ih[j] + b_hh[j] + sum_m W_ih[j][m] * b_in[m]
// ---------------------------------------------------------------------------
__global__ void combine_kernel(const float* __restrict__ W_in,
                               const float* __restrict__ b_in,
                               const float* __restrict__ W_ih,
                               const float* __restrict__ b_ih,
                               const float* __restrict__ b_hh) {
    int idx = blockIdx.x * blockDim.x + threadIdx.x;
    if (idx < HID * CIN) {
        int j = idx >> 5, c = idx & 31;
        float s = 0.f;
        #pragma unroll 8
        for (int m = 0; m < 64; m++) s += W_ih[j * 64 + m] * W_in[m * 32 + c];
        d_Wc[idx] = s;
    }
    if (idx < HID) {
        float s = b_ih[idx] + b_hh[idx];
        #pragma unroll 8
        for (int m = 0; m < 64; m++) s += W_ih[idx * 64 + m] * b_in[m];
        d_bc[idx] = s;
    }
}

// ---------------------------------------------------------------------------
// Kernel B: pre[b][t][j] = bc[j] + sum_c Wc[j][c] * x[b][c][t]
// grid (8, 512). 256 threads: j = tid&127, th = tid>>7; 16 t's per thread
// as 8 f32x2 pairs; ulonglong2 smem loads (2 pairs per LDS.128, broadcast).
// ---------------------------------------------------------------------------
__global__ void __launch_bounds__(256) pre_kernel(const float* __restrict__ x) {
    __shared__ __align__(16) float xs[32 * 32];   // [c][tt]
    int tid = threadIdx.x;
    int b = blockIdx.y;
    int t0 = blockIdx.x * 32;

    #pragma unroll
    for (int i = 0; i < 4; i++) {
        int idx = i * 256 + tid;
        int c = idx >> 5, tt = idx & 31;
        xs[idx] = x[(b * 32 + c) * 256 + t0 + tt];
    }

    int j = tid & 127;
    int th = tid >> 7;

    unsigned long long wd[32];   // duplicated weight pairs (w,w)
    #pragma unroll
    for (int c4 = 0; c4 < 8; c4++) {
        float4 w = *(const float4*)&d_Wc[j * 32 + c4 * 4];
        wd[c4 * 4 + 0] = pack2(w.x, w.x);
        wd[c4 * 4 + 1] = pack2(w.y, w.y);
        wd[c4 * 4 + 2] = pack2(w.z, w.z);
        wd[c4 * 4 + 3] = pack2(w.w, w.w);
    }
    float bcj = d_bc[j];
    unsigned long long bias2 = pack2(bcj, bcj);

    __syncthreads();

    int tbase = th * 16;
    #pragma unroll
    for (int pp = 0; pp < 4; pp++) {
        unsigned long long acc0 = bias2, acc1 = bias2;
        const float* xb = xs + tbase + 4 * pp;
        #pragma unroll
        for (int c = 0; c < 32; c++) {
            ulonglong2 xv = *(const ulonglong2*)(xb + c * 32);
            ffma2(acc0, wd[c], xv.x);
            ffma2(acc1, wd[c], xv.y);
        }
        float v0, v1, v2, v3;
        unpack2(acc0, v0, v1);
        unpack2(acc1, v2, v3);
        int t = t0 + tbase + 4 * pp;
        d_pre[(b * 256 + t + 0) * 128 + j] = v0;
        d_pre[(b * 256 + t + 1) * 128 + j] = v1;
        d_pre[(b * 256 + t + 2) * 128 + j] = v2;
        d_pre[(b * 256 + t + 3) * 128 + j] = v3;
    }
}

// ---------------------------------------------------------------------------
// Kernel C: sequential RNN scan, jpt=4 layout.
// 128 CTAs x 4 batch rows, 256 threads. tid = rg*128 + jg*4 + kc.
// Thread (jg,kc,rg) owns j in {jg, jg+32, jg+64, jg+96} (W slices in 128 regs)
// and batch rows {rg, rg+2}. Per h-load (LDS.128), 4 j's consume it ->
// smem wavefronts drop 4x vs round 2 (the measured bottleneck).
// 3-shuffle reduce-scatter over kc; lane kc finalizes j = kc*32+jg.
// ---------------------------------------------------------------------------
__global__ void __launch_bounds__(256, 1) rnn_kernel(const float* __restrict__ h0,
                                                     const float* __restrict__ W_hh) {
    __shared__ __align__(16) float hsm[4 * 144];

    int tid = threadIdx.x;
    int kc = tid & 3;
    int jg = (tid >> 2) & 31;
    int rg = tid >> 7;          // 0/1; this thread handles rows rg and rg+2
    int r0 = blockIdx.x * 4;

    // W slices: 4 j rows x 32 k as f32x2 pairs (128 regs)
    unsigned long long wp[4][16];
    #pragma unroll
    for (int jj = 0; jj < 4; jj++) {
        const float* wrow = W_hh + (jj * 32 + jg) * 128 + kc * 32;
        #pragma unroll
        for (int i = 0; i < 8; i++) {
            float4 w = *(const float4*)(wrow + i * 4);
            wp[jj][2 * i]     = pack2(w.x, w.y);
            wp[jj][2 * i + 1] = pack2(w.z, w.w);
        }
    }

    for (int i = tid; i < 512; i += 256) {
        int r = i >> 7, k = i & 127;
        hsm[r * 144 + (k >> 5) * 36 + (k & 31)] = h0[(r0 + r) * 128 + k];
    }
    __syncthreads();

    int j_sel = kc * 32 + jg;
    const float* pA = d_pre + (size_t)(r0 + rg) * 256 * 128 + j_sel;
    const float* pB = d_pre + (size_t)(r0 + rg + 2) * 256 * 128 + j_sel;
    float* oA = d_hs + (size_t)(r0 + rg) * 256 * 128 + j_sel;
    float* oB = d_hs + (size_t)(r0 + rg + 2) * 256 * 128 + j_sel;

    const ulonglong2* hbA = (const ulonglong2*)(hsm + rg * 144 + kc * 36);
    const ulonglong2* hbB = (const ulonglong2*)(hsm + (rg + 2) * 144 + kc * 36);
    int sA_idx = rg * 144 + kc * 36 + jg;
    int sB_idx = (rg + 2) * 144 + kc * 36 + jg;

    float pvA = pA[0], pvB = pB[0];

    for (int t = 0; t < 256; t++) {
        int tn = (t + 1) & 255;
        float npA = pA[tn * 128];      // prefetch next step (covers DRAM latency)
        float npB = pB[tn * 128];

        float sAr[4], sBr[4];
        {
            ulonglong2 hv[8];
            #pragma unroll
            for (int i = 0; i < 8; i++) hv[i] = hbA[i];
            #pragma unroll
            for (int jj = 0; jj < 4; jj++) {
                unsigned long long a0 = 0ull, a1 = 0ull;
                #pragma unroll
                for (int i = 0; i < 8; i++) {
                    ffma2(a0, wp[jj][2 * i],     hv[i].x);
                    ffma2(a1, wp[jj][2 * i + 1], hv[i].y);
                }
                unsigned long long as = fadd2(a0, a1);
                float lo, hi; unpack2(as, lo, hi);
                sAr[jj] = lo + hi;
            }
        }
        {
            ulonglong2 hv[8];
            #pragma unroll
            for (int i = 0; i < 8; i++) hv[i] = hbB[i];
            #pragma unroll
            for (int jj = 0; jj < 4; jj++) {
                unsigned long long a0 = 0ull, a1 = 0ull;
                #pragma unroll
                for (int i = 0; i < 8; i++) {
                    ffma2(a0, wp[jj][2 * i],     hv[i].x);
                    ffma2(a1, wp[jj][2 * i + 1], hv[i].y);
                }
                unsigned long long as = fadd2(a0, a1);
                float lo, hi; unpack2(as, lo, hi);
                sBr[jj] = lo + hi;
            }
        }

        // reduce-scatter over the 4 kc lanes: lane kc ends with sum for jj=kc
        bool bit0 = (kc & 1), bit1 = (kc & 2);
        float A_t0 = (bit0 ? sAr[1] : sAr[0]) + __shfl_xor_sync(~0u, bit0 ? sAr[0] : sAr[1], 1);
        float A_t1 = (bit0 ? sAr[3] : sAr[2]) + __shfl_xor_sync(~0u, bit0 ? sAr[2] : sAr[3], 1);
        float selA = (bit1 ? A_t1 : A_t0) + __shfl_xor_sync(~0u, bit1 ? A_t0 : A_t1, 2);
        float B_t0 = (bit0 ? sBr[1] : sBr[0]) + __shfl_xor_sync(~0u, bit0 ? sBr[0] : sBr[1], 1);
        float B_t1 = (bit0 ? sBr[3] : sBr[2]) + __shfl_xor_sync(~0u, bit0 ? sBr[2] : sBr[3], 1);
        float selB = (bit1 ? B_t1 : B_t0) + __shfl_xor_sync(~0u, bit1 ? B_t0 : B_t1, 2);

        float zA = selA + pvA;
        float zB = selB + pvB;
        float eA = __expf(2.0f * zA);
        float hAv = 1.0f - __fdividef(2.0f, eA + 1.0f);
        float eB = __expf(2.0f * zB);
        float hBv = 1.0f - __fdividef(2.0f, eB + 1.0f);

        __syncthreads();   // all reads of h_{t-1} done
        hsm[sA_idx] = hAv;
        hsm[sB_idx] = hBv;
        oA[t * 128] = hAv;
        oB[t * 128] = hBv;
        __syncthreads();   // h_t visible

        pvA = npA; pvB = npB;
    }
}

// ---------------------------------------------------------------------------
// Kernel D: bilinear upsample (16->32, align_corners) + hardswish + mean pool.
// grid (4, 512). smem tile [jj][t] (stride 260 -> conflict-free LDS.128 row
// fetches). Thread (jj,p): 4 output rows; row-interp held in registers; fully
// unrolled ox pass with compile-time x0/x1/wx -> zero LDS in the column pass.
// ---------------------------------------------------------------------------
__global__ void __launch_bounds__(256) pool_kernel() {
    __shared__ __align__(16) float ht[32 * 260];
    __shared__ float partial[8][32];

    int tid = threadIdx.x;
    int b  = blockIdx.y;
    int j0 = blockIdx.x * 32;

    #pragma unroll 4
    for (int i = 0; i < 32; i++) {
        int idx = i * 256 + tid;
        int t = idx >> 5, jj = idx & 31;
        ht[jj * 260 + t] = d_hs[((size_t)b * 256 + t) * 128 + j0 + jj];
    }
    __syncthreads();

    int jj = tid & 31, p = tid >> 5;
    const float* hrow = ht + jj * 260;
    float acc = 0.f;

    #pragma unroll
    for (int ii = 0; ii < 4; ii++) {
        int oy = ii * 8 + p;
        float ysf = (float)(oy * 15) / 31.0f;
        int y0 = (int)ysf;
        float wy = ysf - (float)y0;
        int y1 = min(y0 + 1, 15);

        float ra[16], rb[16];
        const float4* pa = (const float4*)(hrow + y0 * 16);
        const float4* pb = (const float4*)(hrow + y1 * 16);
        #pragma unroll
        for (int q = 0; q < 4; q++) {
            float4 a = pa[q], c = pb[q];
            ra[4 * q + 0] = a.x; ra[4 * q + 1] = a.y; ra[4 * q + 2] = a.z; ra[4 * q + 3] = a.w;
            rb[4 * q + 0] = c.x; rb[4 * q + 1] = c.y; rb[4 * q + 2] = c.z; rb[4 * q + 3] = c.w;
        }
        float rv[16];
        #pragma unroll
        for (int xq = 0; xq < 16; xq++)
            rv[xq] = fmaf(rb[xq] - ra[xq], wy, ra[xq]);

        #pragma unroll
        for (int ox = 0; ox < 32; ox++) {
            const int x0 = (ox * 15) / 31;                    // compile-time
            const int x1 = (x0 + 1 < 16) ? (x0 + 1) : 15;     // compile-time
            const float wx = (float)(ox * 15) / 31.0f - (float)x0;  // folded in f32
            float v = fmaf(rv[x1] - rv[x0], wx, rv[x0]);
            acc = fmaf(v, fminf(fmaxf(v + 3.0f, 0.0f), 6.0f), acc);
        }
    }

    partial[p][jj] = acc;
    __syncthreads();
    if (p == 0) {
        float s = 0.f;
        #pragma unroll
        for (int q = 0; q < 8; q++) s += partial[q][jj];
        d_pooled[b * 128 + j0 + jj] = s * (1.0f / (6.0f * 1024.0f));
    }
}

// ---------------------------------------------------------------------------
// Kernel E: out[b][o] = b_out[o] + sum_j pooled[b][j] * W_out[o][j]
// ---------------------------------------------------------------------------
__global__ void __launch_bounds__(256) out_gemm(const float* __restrict__ W_out,
                                                const float* __restrict__ b_out,
                                                float* __restrict__ out) {
    __shared__ float ws[64][65];
    __shared__ float ps[64][65];

    int tid = threadIdx.x;
    int o0 = blockIdx.x * 64, b0 = blockIdx.y * 64;
    int to = (tid & 15) * 4;
    int tb = (tid >> 4) * 4;

    float acc[4][4] = {};

    for (int k0 = 0; k0 < 128; k0 += 64) {
        __syncthreads();
        #pragma unroll
        for (int i = 0; i < 16; i++) {
            int idx = i * 256 + tid;
            int r = idx >> 6, c = idx & 63;
            ws[r][c] = W_out[(o0 + r) * 128 + k0 + c];
            ps[r][c] = d_pooled[(b0 + r) * 128 + k0 + c];
        }
        __syncthreads();

        #pragma unroll 4
        for (int k = 0; k < 64; k++) {
            float wv[4], pvv[4];
            #pragma unroll
            for (int m = 0; m < 4; m++) { wv[m] = ws[to + m][k]; pvv[m] = ps[tb + m][k]; }
            #pragma unroll
            for (int mb = 0; mb < 4; mb++)
                #pragma unroll
                for (int mo = 0; mo < 4; mo++)
                    acc[mb][mo] = fmaf(pvv[mb], wv[mo], acc[mb][mo]);
        }
    }

    #pragma unroll
    for (int mb = 0; mb < 4; mb++)
        #pragma unroll
        for (int mo = 0; mo < 4; mo++)
            out[(b0 + tb + mb) * 512 + o0 + to + mo] = acc[mb][mo] + b_out[o0 + to + mo];
}

// ---------------------------------------------------------------------------
extern "C" void kernel_launch(void* const* d_in, const int* in_sizes, int n_in,
                              void* d_out, int out_size) {
    const float* x     = (const float*)d_in[0];
    const float* h0    = (const float*)d_in[1];
    const float* W_in  = (const float*)d_in[2];
    const float* b_in  = (const float*)d_in[3];
    const float* W_ih  = (const float*)d_in[4];
    const float* b_ih  = (const float*)d_in[5];
    const float* W_hh  = (const float*)d_in[6];
    const float* b_hh  = (const float*)d_in[7];
    const float* W_out = (const float*)d_in[8];
    const float* b_out = (const float*)d_in[9];
    float* out = (float*)d_out;

    combine_kernel<<<16, 256>>>(W_in, b_in, W_ih, b_ih, b_hh);
    pre_kernel<<<dim3(8, 512), 256>>>(x);
    rnn_kernel<<<128, 256>>>(h0, W_hh);
    pool_kernel<<<dim3(4, 512), 256>>>();
    out_gemm<<<dim3(8, 8), 256>>>(W_out, b_out, out);
}